// round 7
// baseline (speedup 1.0000x reference)
#include <cuda_runtime.h>
#include <cuda_fp16.h>
#include <math.h>
#include <stdint.h>

#define T_TOK 8192
#define D_DIM 1024
#define I_DIM 2816
#define E_NUM 16
#define NSLOT (T_TOK * 2)
#define BM 128
#define BN 64
#define BK 16
#define MAX_MT (NSLOT / BM + E_NUM)   // 144

// pair-permutation: pair p (=k/2) stored at word sigma(p) within an 8-word row
#define SIG(p) (((((p) & 3) << 1)) | ((p) >> 2))

// ================= static device scratch =================
__device__ float    g_probs[T_TOK * E_NUM];
__device__ int      g_topk_idx[NSLOT];
__device__ float    g_topk_w[NSLOT];
__device__ int      g_counts[E_NUM];
__device__ int      g_offsets[E_NUM + 1];
__device__ int      g_cursor[E_NUM];
__device__ int      g_mtile_prefix[E_NUM + 1];
__device__ int      g_slot_token[NSLOT];
__device__ float    g_slot_w[NSLOT];
__device__ int      g_slot_of[NSLOT];

__device__ uint16_t g_H[(size_t)NSLOT * I_DIM];   // fp16 bits (92 MB)
__device__ float    g_Y[(size_t)NSLOT * D_DIM];

// ================= helpers =================
__device__ __forceinline__ uint32_t pack_half2(float a, float b) {
    uint32_t r;
    asm("{ .reg .f16 lo, hi;\n\t"
        "cvt.rn.f16.f32 lo, %1;\n\t"
        "cvt.rn.f16.f32 hi, %2;\n\t"
        "mov.b32 %0, {lo, hi}; }"
        : "=r"(r) : "f"(a), "f"(b));
    return r;
}

#define MMA_F16(d, a0, a1, a2, a3, b0, b1) \
    asm volatile( \
        "mma.sync.aligned.m16n8k16.row.col.f32.f16.f16.f32 " \
        "{%0,%1,%2,%3}, {%4,%5,%6,%7}, {%8,%9}, {%0,%1,%2,%3};" \
        : "+f"((d)[0]), "+f"((d)[1]), "+f"((d)[2]), "+f"((d)[3]) \
        : "r"(a0), "r"(a1), "r"(a2), "r"(a3), "r"(b0), "r"(b1))

// ================= router pipeline (unchanged, validated) =================
__global__ void init_kernel() {
    if (threadIdx.x < E_NUM) g_counts[threadIdx.x] = 0;
}

__global__ void router_kernel(const float* __restrict__ x, const float* __restrict__ gw) {
    int t = blockIdx.x;
    const float* xr = x + (size_t)t * D_DIM;
    float acc[E_NUM];
#pragma unroll
    for (int e = 0; e < E_NUM; e++) acc[e] = 0.f;
    for (int d = threadIdx.x; d < D_DIM; d += 256) {
        float xv = xr[d];
        const float* g = gw + d * E_NUM;
#pragma unroll
        for (int e = 0; e < E_NUM; e++) acc[e] = fmaf(xv, g[e], acc[e]);
    }
#pragma unroll
    for (int e = 0; e < E_NUM; e++)
        for (int off = 16; off > 0; off >>= 1)
            acc[e] += __shfl_down_sync(0xffffffffu, acc[e], off);
    __shared__ float wsum[8][E_NUM];
    int warp = threadIdx.x >> 5, lane = threadIdx.x & 31;
    if (lane == 0)
#pragma unroll
        for (int e = 0; e < E_NUM; e++) wsum[warp][e] = acc[e];
    __syncthreads();
    if (threadIdx.x == 0) {
        float logit[E_NUM];
        for (int e = 0; e < E_NUM; e++) {
            float s = 0.f;
            for (int w = 0; w < 8; w++) s += wsum[w][e];
            logit[e] = s;
        }
        float m = logit[0];
        for (int e = 1; e < E_NUM; e++) m = fmaxf(m, logit[e]);
        float p[E_NUM], sum = 0.f;
        for (int e = 0; e < E_NUM; e++) { p[e] = expf(logit[e] - m); sum += p[e]; }
        float inv = 1.f / sum;
        for (int e = 0; e < E_NUM; e++) { p[e] *= inv; g_probs[t * E_NUM + e] = p[e]; }
        int i0 = 0;
        for (int e = 1; e < E_NUM; e++) if (p[e] > p[i0]) i0 = e;
        int i1 = (i0 == 0) ? 1 : 0;
        for (int e = 0; e < E_NUM; e++) if (e != i0 && p[e] > p[i1]) i1 = e;
        float wn = p[i0] + p[i1];
        g_topk_idx[t * 2 + 0] = i0;
        g_topk_idx[t * 2 + 1] = i1;
        g_topk_w[t * 2 + 0] = p[i0] / wn;
        g_topk_w[t * 2 + 1] = p[i1] / wn;
        atomicAdd(&g_counts[i0], 1);
        atomicAdd(&g_counts[i1], 1);
    }
}

__global__ void offsets_kernel() {
    if (threadIdx.x == 0) {
        int o = 0, mt = 0;
        g_mtile_prefix[0] = 0;
        for (int e = 0; e < E_NUM; e++) {
            g_offsets[e] = o;
            o += g_counts[e];
            mt += (g_counts[e] + BM - 1) / BM;
            g_mtile_prefix[e + 1] = mt;
            g_cursor[e] = 0;
        }
        g_offsets[E_NUM] = o;
    }
}

__global__ void scatter_pos_kernel() {
    int idx = blockIdx.x * 256 + threadIdx.x;
    if (idx >= NSLOT) return;
    int e = g_topk_idx[idx];
    int pos = g_offsets[e] + atomicAdd(&g_cursor[e], 1);
    g_slot_token[pos] = idx >> 1;
    g_slot_w[pos]     = g_topk_w[idx];
    g_slot_of[idx]    = pos;
}

// =====================================================================
// SMEM layout (fp16): each tile row = 16 halves = 8 packed half2 words.
// Pair p (k=2p,2p+1) stored at word SIG(p). A thread (c=lane&3) reads one
// uint2 at word 2c -> pairs c (k=2c,2c+1) and c+4 (k=2c+8,2c+9): exactly
// the m16n8k16 fragment registers (a0,a2) / (b0,b1). Conflict-free LDS.64.
// =====================================================================

// ================= FFN1: H = silu(X Wg) * (X Wu) =================
__global__ __launch_bounds__(128, 2)
void ffn1_kernel(const float* __restrict__ x,
                 const float* __restrict__ Wg,
                 const float* __restrict__ Wu) {
    __shared__ __align__(16) uint32_t As [2][BM * 8];
    __shared__ __align__(16) uint32_t Bgs[2][BN * 8];
    __shared__ __align__(16) uint32_t Bus[2][BN * 8];

    const int mb = blockIdx.x, nb = blockIdx.y;
    if (mb >= g_mtile_prefix[E_NUM]) return;
    int e = 0;
    while (mb >= g_mtile_prefix[e + 1]) e++;
    const int m0   = g_offsets[e] + (mb - g_mtile_prefix[e]) * BM;
    const int mmax = g_offsets[e + 1];

    const int tid = threadIdx.x, lane = tid & 31, wid = tid >> 5;
    const int wm = wid >> 1;            // m offset wm*64
    const int wn = wid & 1;             // n offset wn*32

    // staging thread mapping: q = k-quad (0..3), rbase = row (0..31)
    const int q = tid & 3;
    const int rbase = tid >> 2;
    const int s0 = SIG(2 * q), s1 = SIG(2 * q + 1);

    int  arow[4], atok[4];
    bool av[4];
#pragma unroll
    for (int rr = 0; rr < 4; rr++) {
        arow[rr] = rbase + 32 * rr;
        int gr = m0 + arow[rr];
        av[rr]   = gr < mmax;
        atok[rr] = av[rr] ? g_slot_token[gr] : 0;
    }
    const float* bgp = Wg + (size_t)e * D_DIM * I_DIM + (size_t)nb * BN;
    const float* bup = Wu + (size_t)e * D_DIM * I_DIM + (size_t)nb * BN;

    float accg[4][4][4], accu[4][4][4];
#pragma unroll
    for (int i = 0; i < 4; i++)
#pragma unroll
        for (int j = 0; j < 4; j++)
#pragma unroll
            for (int k = 0; k < 4; k++) { accg[i][j][k] = 0.f; accu[i][j][k] = 0.f; }

    uint32_t pA[4][2], pBg[2][2], pBu[2][2];

#define FFN1_PREFETCH(K0)                                                        \
    do {                                                                         \
        _Pragma("unroll")                                                        \
        for (int rr = 0; rr < 4; rr++) {                                         \
            float4 v = make_float4(0.f, 0.f, 0.f, 0.f);                          \
            if (av[rr])                                                          \
                v = *(const float4*)(x + (size_t)atok[rr] * D_DIM + (K0) + 4 * q); \
            pA[rr][0] = pack_half2(v.x, v.y);                                    \
            pA[rr][1] = pack_half2(v.z, v.w);                                    \
        }                                                                        \
        _Pragma("unroll")                                                        \
        for (int g = 0; g < 2; g++) {                                            \
            int n = rbase + 32 * g;                                              \
            const float* pg = bgp + (size_t)((K0) + 4 * q) * I_DIM + n;          \
            const float* pu = bup + (size_t)((K0) + 4 * q) * I_DIM + n;          \
            pBg[g][0] = pack_half2(pg[0], pg[(size_t)I_DIM]);                    \
            pBg[g][1] = pack_half2(pg[(size_t)2 * I_DIM], pg[(size_t)3 * I_DIM]);\
            pBu[g][0] = pack_half2(pu[0], pu[(size_t)I_DIM]);                    \
            pBu[g][1] = pack_half2(pu[(size_t)2 * I_DIM], pu[(size_t)3 * I_DIM]);\
        }                                                                        \
    } while (0)

#define FFN1_COMMIT(BUF)                                                         \
    do {                                                                         \
        _Pragma("unroll")                                                        \
        for (int rr = 0; rr < 4; rr++) {                                         \
            int ro = arow[rr] * 8;                                               \
            As[BUF][ro + s0] = pA[rr][0];                                        \
            As[BUF][ro + s1] = pA[rr][1];                                        \
        }                                                                        \
        _Pragma("unroll")                                                        \
        for (int g = 0; g < 2; g++) {                                            \
            int no = (rbase + 32 * g) * 8;                                       \
            Bgs[BUF][no + s0] = pBg[g][0];                                       \
            Bgs[BUF][no + s1] = pBg[g][1];                                       \
            Bus[BUF][no + s0] = pBu[g][0];                                       \
            Bus[BUF][no + s1] = pBu[g][1];                                       \
        }                                                                        \
    } while (0)

    FFN1_PREFETCH(0);
    FFN1_COMMIT(0);
    __syncthreads();

    const int c = lane & 3;
    const int lrow = lane >> 2;
    const int NC = D_DIM / BK;          // 64
    for (int kc = 0; kc < NC; kc++) {
        const int cur = kc & 1;
        if (kc + 1 < NC) FFN1_PREFETCH((kc + 1) * BK);

        uint2 alo[4], ahi[4], bg[4], bu[4];
#pragma unroll
        for (int mf = 0; mf < 4; mf++) {
            int r = wm * 64 + mf * 16 + lrow;
            alo[mf] = *(const uint2*)&As[cur][r * 8 + 2 * c];
            ahi[mf] = *(const uint2*)&As[cur][(r + 8) * 8 + 2 * c];
        }
#pragma unroll
        for (int nf = 0; nf < 4; nf++) {
            int n = wn * 32 + nf * 8 + lrow;
            bg[nf] = *(const uint2*)&Bgs[cur][n * 8 + 2 * c];
            bu[nf] = *(const uint2*)&Bus[cur][n * 8 + 2 * c];
        }
#pragma unroll
        for (int mf = 0; mf < 4; mf++)
#pragma unroll
            for (int nf = 0; nf < 4; nf++) {
                MMA_F16(accg[mf][nf], alo[mf].x, ahi[mf].x, alo[mf].y, ahi[mf].y,
                        bg[nf].x, bg[nf].y);
                MMA_F16(accu[mf][nf], alo[mf].x, ahi[mf].x, alo[mf].y, ahi[mf].y,
                        bu[nf].x, bu[nf].y);
            }

        if (kc + 1 < NC) FFN1_COMMIT(cur ^ 1);
        __syncthreads();
    }

    // epilogue: h = silu(g) * u  -> fp16 g_H
#pragma unroll
    for (int mf = 0; mf < 4; mf++) {
        int r0 = m0 + wm * 64 + mf * 16 + lrow;
        int r1 = r0 + 8;
#pragma unroll
        for (int nf = 0; nf < 4; nf++) {
            int col = nb * BN + wn * 32 + nf * 8 + c * 2;
            if (r0 < mmax) {
                float g0 = accg[mf][nf][0], g1 = accg[mf][nf][1];
                float ox = g0 / (1.f + expf(-g0)) * accu[mf][nf][0];
                float oy = g1 / (1.f + expf(-g1)) * accu[mf][nf][1];
                *(uint32_t*)(g_H + (size_t)r0 * I_DIM + col) = pack_half2(ox, oy);
            }
            if (r1 < mmax) {
                float g2 = accg[mf][nf][2], g3 = accg[mf][nf][3];
                float ox = g2 / (1.f + expf(-g2)) * accu[mf][nf][2];
                float oy = g3 / (1.f + expf(-g3)) * accu[mf][nf][3];
                *(uint32_t*)(g_H + (size_t)r1 * I_DIM + col) = pack_half2(ox, oy);
            }
        }
    }
}

// ================= FFN2: Y = (H Wd) * slot_w =================
__global__ __launch_bounds__(128, 2)
void ffn2_kernel(const float* __restrict__ Wd) {
    __shared__ __align__(16) uint32_t As[2][BM * 8];
    __shared__ __align__(16) uint32_t Bs[2][BN * 8];

    const int mb = blockIdx.x, nb = blockIdx.y;
    if (mb >= g_mtile_prefix[E_NUM]) return;
    int e = 0;
    while (mb >= g_mtile_prefix[e + 1]) e++;
    const int m0   = g_offsets[e] + (mb - g_mtile_prefix[e]) * BM;
    const int mmax = g_offsets[e + 1];

    const int tid = threadIdx.x, lane = tid & 31, wid = tid >> 5;
    const int wm = wid >> 1, wn = wid & 1;

    const int q = tid & 3;
    const int rbase = tid >> 2;
    const int s0 = SIG(2 * q), s1 = SIG(2 * q + 1);

    int  arow[4];
    bool av[4];
#pragma unroll
    for (int rr = 0; rr < 4; rr++) {
        arow[rr] = rbase + 32 * rr;
        av[rr]   = (m0 + arow[rr]) < mmax;
    }
    const float* bp = Wd + (size_t)e * I_DIM * D_DIM + (size_t)nb * BN;

    float acc[4][4][4];
#pragma unroll
    for (int i = 0; i < 4; i++)
#pragma unroll
        for (int j = 0; j < 4; j++)
#pragma unroll
            for (int k = 0; k < 4; k++) acc[i][j][k] = 0.f;

    uint2    pA[4];
    uint32_t pB[2][2];

#define FFN2_PREFETCH(K0)                                                        \
    do {                                                                         \
        _Pragma("unroll")                                                        \
        for (int rr = 0; rr < 4; rr++) {                                         \
            pA[rr] = make_uint2(0u, 0u);                                         \
            if (av[rr])                                                          \
                pA[rr] = *(const uint2*)(g_H +                                   \
                         (size_t)(m0 + arow[rr]) * I_DIM + (K0) + 4 * q);        \
        }                                                                        \
        _Pragma("unroll")                                                        \
        for (int g = 0; g < 2; g++) {                                            \
            int n = rbase + 32 * g;                                              \
            const float* p = bp + (size_t)((K0) + 4 * q) * D_DIM + n;            \
            pB[g][0] = pack_half2(p[0], p[(size_t)D_DIM]);                       \
            pB[g][1] = pack_half2(p[(size_t)2 * D_DIM], p[(size_t)3 * D_DIM]);   \
        }                                                                        \
    } while (0)

#define FFN2_COMMIT(BUF)                                                         \
    do {                                                                         \
        _Pragma("unroll")                                                        \
        for (int rr = 0; rr < 4; rr++) {                                         \
            int ro = arow[rr] * 8;                                               \
            As[BUF][ro + s0] = pA[rr].x;                                         \
            As[BUF][ro + s1] = pA[rr].y;                                         \
        }                                                                        \
        _Pragma("unroll")                                                        \
        for (int g = 0; g < 2; g++) {                                            \
            int no = (rbase + 32 * g) * 8;                                       \
            Bs[BUF][no + s0] = pB[g][0];                                         \
            Bs[BUF][no + s1] = pB[g][1];                                         \
        }                                                                        \
    } while (0)

    FFN2_PREFETCH(0);
    FFN2_COMMIT(0);
    __syncthreads();

    const int c = lane & 3;
    const int lrow = lane >> 2;
    const int NC = I_DIM / BK;          // 176
    for (int kc = 0; kc < NC; kc++) {
        const int cur = kc & 1;
        if (kc + 1 < NC) FFN2_PREFETCH((kc + 1) * BK);

        uint2 alo[4], ahi[4], b[4];
#pragma unroll
        for (int mf = 0; mf < 4; mf++) {
            int r = wm * 64 + mf * 16 + lrow;
            alo[mf] = *(const uint2*)&As[cur][r * 8 + 2 * c];
            ahi[mf] = *(const uint2*)&As[cur][(r + 8) * 8 + 2 * c];
        }
#pragma unroll
        for (int nf = 0; nf < 4; nf++) {
            int n = wn * 32 + nf * 8 + lrow;
            b[nf] = *(const uint2*)&Bs[cur][n * 8 + 2 * c];
        }
#pragma unroll
        for (int mf = 0; mf < 4; mf++)
#pragma unroll
            for (int nf = 0; nf < 4; nf++)
                MMA_F16(acc[mf][nf], alo[mf].x, ahi[mf].x, alo[mf].y, ahi[mf].y,
                        b[nf].x, b[nf].y);

        if (kc + 1 < NC) FFN2_COMMIT(cur ^ 1);
        __syncthreads();
    }

#pragma unroll
    for (int mf = 0; mf < 4; mf++) {
        int r0 = m0 + wm * 64 + mf * 16 + lrow;
        int r1 = r0 + 8;
        float w0 = (r0 < mmax) ? g_slot_w[r0] : 0.f;
        float w1 = (r1 < mmax) ? g_slot_w[r1] : 0.f;
#pragma unroll
        for (int nf = 0; nf < 4; nf++) {
            int col = nb * BN + wn * 32 + nf * 8 + c * 2;
            if (r0 < mmax)
                *(float2*)(g_Y + (size_t)r0 * D_DIM + col) =
                    make_float2(acc[mf][nf][0] * w0, acc[mf][nf][1] * w0);
            if (r1 < mmax)
                *(float2*)(g_Y + (size_t)r1 * D_DIM + col) =
                    make_float2(acc[mf][nf][2] * w1, acc[mf][nf][3] * w1);
        }
    }
}

// ================= combine + aux (unchanged) =================
__global__ void combine_kernel(float* __restrict__ out) {
    int t = blockIdx.x;
    int s0 = g_slot_of[t * 2 + 0];
    int s1 = g_slot_of[t * 2 + 1];
    const float4* y0 = (const float4*)(g_Y + (size_t)s0 * D_DIM);
    const float4* y1 = (const float4*)(g_Y + (size_t)s1 * D_DIM);
    float4 a = y0[threadIdx.x], b = y1[threadIdx.x];
    ((float4*)(out + (size_t)t * D_DIM))[threadIdx.x] =
        make_float4(a.x + b.x, a.y + b.y, a.z + b.z, a.w + b.w);
}

__global__ void aux_kernel(float* __restrict__ out, int out_size) {
    __shared__ float red[256];
    __shared__ float esum[E_NUM];
    float part[E_NUM];
#pragma unroll
    for (int e = 0; e < E_NUM; e++) part[e] = 0.f;
    for (int t = threadIdx.x; t < T_TOK; t += 256)
#pragma unroll
        for (int e = 0; e < E_NUM; e++) part[e] += g_probs[t * E_NUM + e];
    for (int e = 0; e < E_NUM; e++) {
        red[threadIdx.x] = part[e];
        __syncthreads();
        for (int off = 128; off > 0; off >>= 1) {
            if (threadIdx.x < off) red[threadIdx.x] += red[threadIdx.x + off];
            __syncthreads();
        }
        if (threadIdx.x == 0) esum[e] = red[0];
        __syncthreads();
    }
    if (threadIdx.x == 0) {
        float aux = 0.f;
        for (int e = 0; e < E_NUM; e++)
            aux += ((float)g_counts[e] / (float)T_TOK) * (esum[e] / (float)T_TOK);
        aux *= 0.01f * (float)E_NUM;
        if (out_size > T_TOK * D_DIM) out[(size_t)T_TOK * D_DIM] = aux;
    }
}

// ================= launch =================
extern "C" void kernel_launch(void* const* d_in, const int* in_sizes, int n_in,
                              void* d_out, int out_size) {
    const float* x      = (const float*)d_in[0];
    const float* gate_w = (const float*)d_in[1];
    const float* Wg     = (const float*)d_in[2];
    const float* Wu     = (const float*)d_in[3];
    const float* Wd     = (const float*)d_in[4];
    float* out = (float*)d_out;

    init_kernel<<<1, 32>>>();
    router_kernel<<<T_TOK, 256>>>(x, gate_w);
    offsets_kernel<<<1, 32>>>();
    scatter_pos_kernel<<<(NSLOT + 255) / 256, 256>>>();

    dim3 g1(MAX_MT, I_DIM / BN);   // 144 x 44
    ffn1_kernel<<<g1, 128>>>(x, Wg, Wu);
    dim3 g2(MAX_MT, D_DIM / BN);   // 144 x 16
    ffn2_kernel<<<g2, 128>>>(Wd);

    combine_kernel<<<T_TOK, 256>>>(out);
    aux_kernel<<<1, 256>>>(out, out_size);
}

// round 8
// speedup vs baseline: 2.1012x; 2.1012x over previous
#include <cuda_runtime.h>
#include <cuda_fp16.h>
#include <math.h>
#include <stdint.h>

#define T_TOK 8192
#define D_DIM 1024
#define I_DIM 2816
#define E_NUM 16
#define NSLOT (T_TOK * 2)
#define BM 128
#define BN 64
#define BK 32
#define NSTAGE 4
#define MAX_MT (NSLOT / BM + E_NUM)   // 144

// ================= static device scratch =================
__device__ float    g_probs[T_TOK * E_NUM];
__device__ int      g_topk_idx[NSLOT];
__device__ float    g_topk_w[NSLOT];
__device__ int      g_counts[E_NUM];
__device__ int      g_offsets[E_NUM + 1];
__device__ int      g_cursor[E_NUM];
__device__ int      g_mtile_prefix[E_NUM + 1];
__device__ int      g_slot_token[NSLOT];
__device__ float    g_slot_w[NSLOT];
__device__ int      g_slot_of[NSLOT];

__device__ uint16_t g_xh [(size_t)T_TOK * D_DIM];
__device__ uint16_t g_Wgh[(size_t)E_NUM * D_DIM * I_DIM];
__device__ uint16_t g_Wuh[(size_t)E_NUM * D_DIM * I_DIM];
__device__ uint16_t g_Wdh[(size_t)E_NUM * I_DIM * D_DIM];
__device__ uint16_t g_H  [(size_t)NSLOT * I_DIM];
__device__ float    g_Y  [(size_t)NSLOT * D_DIM];

// ================= helpers =================
__device__ __forceinline__ uint32_t f2h2(float lo, float hi) {
    uint32_t r;
    asm("cvt.rn.f16x2.f32 %0, %1, %2;" : "=r"(r) : "f"(hi), "f"(lo));
    return r;
}
__device__ __forceinline__ uint32_t smem_u32(const void* p) {
    uint32_t a;
    asm("{ .reg .u64 t; cvta.to.shared.u64 t, %1; cvt.u32.u64 %0, t; }" : "=r"(a) : "l"(p));
    return a;
}
#define CP_ASYNC16(dst, src, sz) \
    asm volatile("cp.async.cg.shared.global [%0], [%1], 16, %2;" \
                 :: "r"(dst), "l"(src), "r"(sz) : "memory")
#define CP_COMMIT() asm volatile("cp.async.commit_group;" ::: "memory")
#define CP_WAIT(n)  asm volatile("cp.async.wait_group %0;" :: "n"(n) : "memory")
#define LDSM_X4(r0, r1, r2, r3, addr) \
    asm volatile("ldmatrix.sync.aligned.m8n8.x4.shared.b16 {%0,%1,%2,%3}, [%4];" \
                 : "=r"(r0), "=r"(r1), "=r"(r2), "=r"(r3) : "r"(addr))
#define LDSM_X4_T(r0, r1, r2, r3, addr) \
    asm volatile("ldmatrix.sync.aligned.m8n8.x4.trans.shared.b16 {%0,%1,%2,%3}, [%4];" \
                 : "=r"(r0), "=r"(r1), "=r"(r2), "=r"(r3) : "r"(addr))
#define MMA_F16(d, a, b0, b1) \
    asm volatile( \
        "mma.sync.aligned.m16n8k16.row.col.f32.f16.f16.f32 " \
        "{%0,%1,%2,%3}, {%4,%5,%6,%7}, {%8,%9}, {%0,%1,%2,%3};" \
        : "+f"((d)[0]), "+f"((d)[1]), "+f"((d)[2]), "+f"((d)[3]) \
        : "r"((a)[0]), "r"((a)[1]), "r"((a)[2]), "r"((a)[3]), "r"(b0), "r"(b1))

// ================= one-time fp32 -> fp16 convert =================
__global__ void convert_fp16_kernel(const float4* __restrict__ src, uint2* __restrict__ dst) {
    size_t i = (size_t)blockIdx.x * 256 + threadIdx.x;
    float4 v = src[i];
    dst[i] = make_uint2(f2h2(v.x, v.y), f2h2(v.z, v.w));
}

// ================= router pipeline (validated) =================
__global__ void init_kernel() {
    if (threadIdx.x < E_NUM) g_counts[threadIdx.x] = 0;
}

__global__ void router_kernel(const float* __restrict__ x, const float* __restrict__ gw) {
    int t = blockIdx.x;
    const float* xr = x + (size_t)t * D_DIM;
    float acc[E_NUM];
#pragma unroll
    for (int e = 0; e < E_NUM; e++) acc[e] = 0.f;
    for (int d = threadIdx.x; d < D_DIM; d += 256) {
        float xv = xr[d];
        const float* g = gw + d * E_NUM;
#pragma unroll
        for (int e = 0; e < E_NUM; e++) acc[e] = fmaf(xv, g[e], acc[e]);
    }
#pragma unroll
    for (int e = 0; e < E_NUM; e++)
        for (int off = 16; off > 0; off >>= 1)
            acc[e] += __shfl_down_sync(0xffffffffu, acc[e], off);
    __shared__ float wsum[8][E_NUM];
    int warp = threadIdx.x >> 5, lane = threadIdx.x & 31;
    if (lane == 0)
#pragma unroll
        for (int e = 0; e < E_NUM; e++) wsum[warp][e] = acc[e];
    __syncthreads();
    if (threadIdx.x == 0) {
        float logit[E_NUM];
        for (int e = 0; e < E_NUM; e++) {
            float s = 0.f;
            for (int w = 0; w < 8; w++) s += wsum[w][e];
            logit[e] = s;
        }
        float m = logit[0];
        for (int e = 1; e < E_NUM; e++) m = fmaxf(m, logit[e]);
        float p[E_NUM], sum = 0.f;
        for (int e = 0; e < E_NUM; e++) { p[e] = expf(logit[e] - m); sum += p[e]; }
        float inv = 1.f / sum;
        for (int e = 0; e < E_NUM; e++) { p[e] *= inv; g_probs[t * E_NUM + e] = p[e]; }
        int i0 = 0;
        for (int e = 1; e < E_NUM; e++) if (p[e] > p[i0]) i0 = e;
        int i1 = (i0 == 0) ? 1 : 0;
        for (int e = 0; e < E_NUM; e++) if (e != i0 && p[e] > p[i1]) i1 = e;
        float wn = p[i0] + p[i1];
        g_topk_idx[t * 2 + 0] = i0;
        g_topk_idx[t * 2 + 1] = i1;
        g_topk_w[t * 2 + 0] = p[i0] / wn;
        g_topk_w[t * 2 + 1] = p[i1] / wn;
        atomicAdd(&g_counts[i0], 1);
        atomicAdd(&g_counts[i1], 1);
    }
}

__global__ void offsets_kernel() {
    if (threadIdx.x == 0) {
        int o = 0, mt = 0;
        g_mtile_prefix[0] = 0;
        for (int e = 0; e < E_NUM; e++) {
            g_offsets[e] = o;
            o += g_counts[e];
            mt += (g_counts[e] + BM - 1) / BM;
            g_mtile_prefix[e + 1] = mt;
            g_cursor[e] = 0;
        }
        g_offsets[E_NUM] = o;
    }
}

__global__ void scatter_pos_kernel() {
    int idx = blockIdx.x * 256 + threadIdx.x;
    if (idx >= NSLOT) return;
    int e = g_topk_idx[idx];
    int pos = g_offsets[e] + atomicAdd(&g_cursor[e], 1);
    g_slot_token[pos] = idx >> 1;
    g_slot_w[pos]     = g_topk_w[idx];
    g_slot_of[idx]    = pos;
}

// SMEM formats: A row r (64B): chunk c at r*64 + 16*(c ^ ((r>>1)&3)).
//               B k-row (128B): chunk c at k*128 + 16*(c ^ (k&7)).

// ================= FFN1: H = silu(X Wg) * (X Wu) =================
__global__ __launch_bounds__(128, 2)
void ffn1_kernel() {
    extern __shared__ __align__(16) uint8_t smem[];
    const uint32_t sbase = smem_u32(smem);   // per stage 16KB: A@0, Bg@8192, Bu@12288

    const int mb = blockIdx.x, nb = blockIdx.y;
    if (mb >= g_mtile_prefix[E_NUM]) return;
    int e = 0;
    while (mb >= g_mtile_prefix[e + 1]) e++;
    const int m0   = g_offsets[e] + (mb - g_mtile_prefix[e]) * BM;
    const int mmax = g_offsets[e + 1];

    const int tid = threadIdx.x, lane = tid & 31, wid = tid >> 5;
    const int wm = wid >> 1, wn = wid & 1;

    const int rbase = tid >> 2, chA = tid & 3;
    const int kbB = tid >> 3, chB = tid & 7;
    const char* aSrc[4];
    uint32_t    aDst[4], aSz[4];
#pragma unroll
    for (int rr = 0; rr < 4; rr++) {
        int row = rbase + 32 * rr;
        int gr  = m0 + row;
        int ok  = gr < mmax;
        int tok = ok ? g_slot_token[gr] : 0;
        aSrc[rr] = (const char*)g_xh + (size_t)tok * D_DIM * 2 + chA * 16;
        aDst[rr] = row * 64 + 16 * (chA ^ ((row >> 1) & 3));
        aSz[rr]  = ok ? 16u : 0u;
    }
    const char* gSrc[2];
    const char* uSrc[2];
    uint32_t    bDst[2];
#pragma unroll
    for (int i = 0; i < 2; i++) {
        int k = kbB + 16 * i;
        size_t off = (((size_t)e * D_DIM + k) * I_DIM + (size_t)nb * BN) * 2 + chB * 16;
        gSrc[i] = (const char*)g_Wgh + off;
        uSrc[i] = (const char*)g_Wuh + off;
        bDst[i] = k * 128 + 16 * (chB ^ (k & 7));
    }

#define FFN1_ISSUE(BUF, KC)                                                     \
    do {                                                                        \
        uint32_t sb = sbase + (BUF) * 16384;                                    \
        _Pragma("unroll")                                                       \
        for (int rr = 0; rr < 4; rr++)                                          \
            CP_ASYNC16(sb + aDst[rr], aSrc[rr] + (size_t)(KC) * 64, aSz[rr]);   \
        _Pragma("unroll")                                                       \
        for (int i = 0; i < 2; i++) {                                           \
            size_t ko = (size_t)(KC) * BK * I_DIM * 2;                          \
            CP_ASYNC16(sb + 8192  + bDst[i], gSrc[i] + ko, 16u);                \
            CP_ASYNC16(sb + 12288 + bDst[i], uSrc[i] + ko, 16u);                \
        }                                                                       \
    } while (0)

    float accg[4][4][4], accu[4][4][4];
#pragma unroll
    for (int i = 0; i < 4; i++)
#pragma unroll
        for (int j = 0; j < 4; j++)
#pragma unroll
            for (int k = 0; k < 4; k++) { accg[i][j][k] = 0.f; accu[i][j][k] = 0.f; }

    const int NC = D_DIM / BK;   // 32
#pragma unroll
    for (int s = 0; s < NSTAGE - 1; s++) { FFN1_ISSUE(s, s); CP_COMMIT(); }

    for (int kc = 0; kc < NC; kc++) {
        CP_WAIT(NSTAGE - 2);
        __syncthreads();
        int nk = kc + NSTAGE - 1;
        if (nk < NC) FFN1_ISSUE(nk & (NSTAGE - 1), nk);
        CP_COMMIT();

        const uint32_t abase = sbase + (kc & (NSTAGE - 1)) * 16384;
#pragma unroll
        for (int ks = 0; ks < 2; ks++) {
            uint32_t a[4][4];
#pragma unroll
            for (int mf = 0; mf < 4; mf++) {
                int r  = wm * 64 + mf * 16 + (lane & 15);
                int lc = ks * 2 + (lane >> 4);
                LDSM_X4(a[mf][0], a[mf][1], a[mf][2], a[mf][3],
                        abase + r * 64 + 16 * (lc ^ ((r >> 1) & 3)));
            }
            uint32_t bg[2][4], bu[2][4];
#pragma unroll
            for (int np = 0; np < 2; np++) {
                int k  = ks * 16 + ((lane >> 3) & 1) * 8 + (lane & 7);
                int nl = wn * 32 + np * 16 + (lane >> 4) * 8;
                uint32_t off = k * 128 + 16 * ((nl >> 3) ^ (k & 7));
                LDSM_X4_T(bg[np][0], bg[np][1], bg[np][2], bg[np][3], abase + 8192 + off);
                LDSM_X4_T(bu[np][0], bu[np][1], bu[np][2], bu[np][3], abase + 12288 + off);
            }
#pragma unroll
            for (int mf = 0; mf < 4; mf++)
#pragma unroll
                for (int nf = 0; nf < 4; nf++) {
                    MMA_F16(accg[mf][nf], a[mf], bg[nf >> 1][(nf & 1) * 2],
                            bg[nf >> 1][(nf & 1) * 2 + 1]);
                    MMA_F16(accu[mf][nf], a[mf], bu[nf >> 1][(nf & 1) * 2],
                            bu[nf >> 1][(nf & 1) * 2 + 1]);
                }
        }
    }

#pragma unroll
    for (int mf = 0; mf < 4; mf++) {
        int r0 = m0 + wm * 64 + mf * 16 + (lane >> 2);
        int r1 = r0 + 8;
#pragma unroll
        for (int nf = 0; nf < 4; nf++) {
            int col = nb * BN + wn * 32 + nf * 8 + (lane & 3) * 2;
            if (r0 < mmax) {
                float g0 = accg[mf][nf][0], g1 = accg[mf][nf][1];
                float h0 = g0 / (1.f + expf(-g0)) * accu[mf][nf][0];
                float h1 = g1 / (1.f + expf(-g1)) * accu[mf][nf][1];
                *(uint32_t*)(g_H + (size_t)r0 * I_DIM + col) = f2h2(h0, h1);
            }
            if (r1 < mmax) {
                float g2 = accg[mf][nf][2], g3 = accg[mf][nf][3];
                float h2 = g2 / (1.f + expf(-g2)) * accu[mf][nf][2];
                float h3 = g3 / (1.f + expf(-g3)) * accu[mf][nf][3];
                *(uint32_t*)(g_H + (size_t)r1 * I_DIM + col) = f2h2(h2, h3);
            }
        }
    }
}

// ================= FFN2: Y = (H Wd) * slot_w =================
__global__ __launch_bounds__(128, 3)
void ffn2_kernel() {
    extern __shared__ __align__(16) uint8_t smem[];
    const uint32_t sbase = smem_u32(smem);   // per stage 12KB: A@0, B@8192

    const int mb = blockIdx.x, nb = blockIdx.y;
    if (mb >= g_mtile_prefix[E_NUM]) return;
    int e = 0;
    while (mb >= g_mtile_prefix[e + 1]) e++;
    const int m0   = g_offsets[e] + (mb - g_mtile_prefix[e]) * BM;
    const int mmax = g_offsets[e + 1];

    const int tid = threadIdx.x, lane = tid & 31, wid = tid >> 5;
    const int wm = wid >> 1, wn = wid & 1;

    const int rbase = tid >> 2, chA = tid & 3;
    const int kbB = tid >> 3, chB = tid & 7;
    const char* aSrc[4];
    uint32_t    aDst[4], aSz[4];
#pragma unroll
    for (int rr = 0; rr < 4; rr++) {
        int row = rbase + 32 * rr;
        int gr  = m0 + row;
        int ok  = gr < mmax;
        aSrc[rr] = (const char*)g_H + (size_t)(ok ? gr : 0) * I_DIM * 2 + chA * 16;
        aDst[rr] = row * 64 + 16 * (chA ^ ((row >> 1) & 3));
        aSz[rr]  = ok ? 16u : 0u;
    }
    const char* dSrc[2];
    uint32_t    bDst[2];
#pragma unroll
    for (int i = 0; i < 2; i++) {
        int k = kbB + 16 * i;
        dSrc[i] = (const char*)g_Wdh +
                  (((size_t)e * I_DIM + k) * D_DIM + (size_t)nb * BN) * 2 + chB * 16;
        bDst[i] = k * 128 + 16 * (chB ^ (k & 7));
    }

#define FFN2_ISSUE(BUF, KC)                                                     \
    do {                                                                        \
        uint32_t sb = sbase + (BUF) * 12288;                                    \
        _Pragma("unroll")                                                       \
        for (int rr = 0; rr < 4; rr++)                                          \
            CP_ASYNC16(sb + aDst[rr], aSrc[rr] + (size_t)(KC) * 64, aSz[rr]);   \
        _Pragma("unroll")                                                       \
        for (int i = 0; i < 2; i++)                                             \
            CP_ASYNC16(sb + 8192 + bDst[i],                                     \
                       dSrc[i] + (size_t)(KC) * BK * D_DIM * 2, 16u);           \
    } while (0)

    float acc[4][4][4];
#pragma unroll
    for (int i = 0; i < 4; i++)
#pragma unroll
        for (int j = 0; j < 4; j++)
#pragma unroll
            for (int k = 0; k < 4; k++) acc[i][j][k] = 0.f;

    const int NC = I_DIM / BK;   // 88
#pragma unroll
    for (int s = 0; s < NSTAGE - 1; s++) { FFN2_ISSUE(s, s); CP_COMMIT(); }

    for (int kc = 0; kc < NC; kc++) {
        CP_WAIT(NSTAGE - 2);
        __syncthreads();
        int nk = kc + NSTAGE - 1;
        if (nk < NC) FFN2_ISSUE(nk & (NSTAGE - 1), nk);
        CP_COMMIT();

        const uint32_t abase = sbase + (kc & (NSTAGE - 1)) * 12288;
#pragma unroll
        for (int ks = 0; ks < 2; ks++) {
            uint32_t a[4][4];
#pragma unroll
            for (int mf = 0; mf < 4; mf++) {
                int r  = wm * 64 + mf * 16 + (lane & 15);
                int lc = ks * 2 + (lane >> 4);
                LDSM_X4(a[mf][0], a[mf][1], a[mf][2], a[mf][3],
                        abase + r * 64 + 16 * (lc ^ ((r >> 1) & 3)));
            }
            uint32_t b[2][4];
#pragma unroll
            for (int np = 0; np < 2; np++) {
                int k  = ks * 16 + ((lane >> 3) & 1) * 8 + (lane & 7);
                int nl = wn * 32 + np * 16 + (lane >> 4) * 8;
                LDSM_X4_T(b[np][0], b[np][1], b[np][2], b[np][3],
                          abase + 8192 + k * 128 + 16 * ((nl >> 3) ^ (k & 7)));
            }
#pragma unroll
            for (int mf = 0; mf < 4; mf++)
#pragma unroll
                for (int nf = 0; nf < 4; nf++)
                    MMA_F16(acc[mf][nf], a[mf], b[nf >> 1][(nf & 1) * 2],
                            b[nf >> 1][(nf & 1) * 2 + 1]);
        }
    }

#pragma unroll
    for (int mf = 0; mf < 4; mf++) {
        int r0 = m0 + wm * 64 + mf * 16 + (lane >> 2);
        int r1 = r0 + 8;
        float w0 = (r0 < mmax) ? g_slot_w[r0] : 0.f;
        float w1 = (r1 < mmax) ? g_slot_w[r1] : 0.f;
#pragma unroll
        for (int nf = 0; nf < 4; nf++) {
            int col = nb * BN + wn * 32 + nf * 8 + (lane & 3) * 2;
            if (r0 < mmax)
                *(float2*)(g_Y + (size_t)r0 * D_DIM + col) =
                    make_float2(acc[mf][nf][0] * w0, acc[mf][nf][1] * w0);
            if (r1 < mmax)
                *(float2*)(g_Y + (size_t)r1 * D_DIM + col) =
                    make_float2(acc[mf][nf][2] * w1, acc[mf][nf][3] * w1);
        }
    }
}

// ================= combine + aux =================
__global__ void combine_kernel(float* __restrict__ out) {
    int t = blockIdx.x;
    int s0 = g_slot_of[t * 2 + 0];
    int s1 = g_slot_of[t * 2 + 1];
    const float4* y0 = (const float4*)(g_Y + (size_t)s0 * D_DIM);
    const float4* y1 = (const float4*)(g_Y + (size_t)s1 * D_DIM);
    float4 a = y0[threadIdx.x], b = y1[threadIdx.x];
    ((float4*)(out + (size_t)t * D_DIM))[threadIdx.x] =
        make_float4(a.x + b.x, a.y + b.y, a.z + b.z, a.w + b.w);
}

__global__ void aux_kernel(float* __restrict__ out, int out_size) {
    __shared__ float red[256];
    __shared__ float esum[E_NUM];
    float part[E_NUM];
#pragma unroll
    for (int e = 0; e < E_NUM; e++) part[e] = 0.f;
    for (int t = threadIdx.x; t < T_TOK; t += 256)
#pragma unroll
        for (int e = 0; e < E_NUM; e++) part[e] += g_probs[t * E_NUM + e];
    for (int e = 0; e < E_NUM; e++) {
        red[threadIdx.x] = part[e];
        __syncthreads();
        for (int off = 128; off > 0; off >>= 1) {
            if (threadIdx.x < off) red[threadIdx.x] += red[threadIdx.x + off];
            __syncthreads();
        }
        if (threadIdx.x == 0) esum[e] = red[0];
        __syncthreads();
    }
    if (threadIdx.x == 0) {
        float aux = 0.f;
        for (int e = 0; e < E_NUM; e++)
            aux += ((float)g_counts[e] / (float)T_TOK) * (esum[e] / (float)T_TOK);
        aux *= 0.01f * (float)E_NUM;
        if (out_size > T_TOK * D_DIM) out[(size_t)T_TOK * D_DIM] = aux;
    }
}

// ================= launch =================
extern "C" void kernel_launch(void* const* d_in, const int* in_sizes, int n_in,
                              void* d_out, int out_size) {
    const float* x      = (const float*)d_in[0];
    const float* gate_w = (const float*)d_in[1];
    const float* Wg     = (const float*)d_in[2];
    const float* Wu     = (const float*)d_in[3];
    const float* Wd     = (const float*)d_in[4];
    float* out = (float*)d_out;

    uint16_t* dxh;  cudaGetSymbolAddress((void**)&dxh,  g_xh);
    uint16_t* dWg;  cudaGetSymbolAddress((void**)&dWg,  g_Wgh);
    uint16_t* dWu;  cudaGetSymbolAddress((void**)&dWu,  g_Wuh);
    uint16_t* dWd;  cudaGetSymbolAddress((void**)&dWd,  g_Wdh);

    static int attr_done = 0;
    if (!attr_done) {
        cudaFuncSetAttribute(ffn1_kernel, cudaFuncAttributeMaxDynamicSharedMemorySize,
                             NSTAGE * 16384);
        cudaFuncSetAttribute(ffn2_kernel, cudaFuncAttributeMaxDynamicSharedMemorySize,
                             NSTAGE * 12288);
        attr_done = 1;
    }

    const int WQ = E_NUM * D_DIM * I_DIM / 4 / 256;   // 45056 blocks
    convert_fp16_kernel<<<T_TOK * D_DIM / 4 / 256, 256>>>((const float4*)x, (uint2*)dxh);
    convert_fp16_kernel<<<WQ, 256>>>((const float4*)Wg, (uint2*)dWg);
    convert_fp16_kernel<<<WQ, 256>>>((const float4*)Wu, (uint2*)dWu);
    convert_fp16_kernel<<<WQ, 256>>>((const float4*)Wd, (uint2*)dWd);

    init_kernel<<<1, 32>>>();
    router_kernel<<<T_TOK, 256>>>(x, gate_w);
    offsets_kernel<<<1, 32>>>();
    scatter_pos_kernel<<<(NSLOT + 255) / 256, 256>>>();

    dim3 g1(MAX_MT, I_DIM / BN);   // 144 x 44
    ffn1_kernel<<<g1, 128, NSTAGE * 16384>>>();
    dim3 g2(MAX_MT, D_DIM / BN);   // 144 x 16
    ffn2_kernel<<<g2, 128, NSTAGE * 12288>>>();

    combine_kernel<<<T_TOK, 256>>>(out);
    aux_kernel<<<1, 256>>>(out, out_size);
}

// round 9
// speedup vs baseline: 2.1286x; 1.0130x over previous
#include <cuda_runtime.h>
#include <cuda_fp16.h>
#include <math.h>
#include <stdint.h>

#define T_TOK 8192
#define D_DIM 1024
#define I_DIM 2816
#define E_NUM 16
#define NSLOT (T_TOK * 2)
#define BM 128
#define BN 64
#define BK 32
#define NSTAGE 4
#define MAX_MT (NSLOT / BM + E_NUM)   // 144

// ================= static device scratch =================
__device__ float    g_probs[T_TOK * E_NUM];
__device__ int      g_topk_idx[NSLOT];
__device__ float    g_topk_w[NSLOT];
__device__ int      g_counts[E_NUM];
__device__ int      g_offsets[E_NUM + 1];
__device__ int      g_cursor[E_NUM];
__device__ int      g_mtile_prefix[E_NUM + 1];
__device__ int      g_slot_token[NSLOT];
__device__ float    g_slot_w[NSLOT];
__device__ int      g_slot_of[NSLOT];

__device__ uint16_t g_xh [(size_t)T_TOK * D_DIM];
__device__ uint16_t g_Wgh[(size_t)E_NUM * D_DIM * I_DIM];
__device__ uint16_t g_Wuh[(size_t)E_NUM * D_DIM * I_DIM];
__device__ uint16_t g_Wdh[(size_t)E_NUM * I_DIM * D_DIM];
__device__ uint16_t g_H  [(size_t)NSLOT * I_DIM];
__device__ float    g_Y  [(size_t)NSLOT * D_DIM];

// ================= helpers =================
__device__ __forceinline__ uint32_t f2h2(float lo, float hi) {
    uint32_t r;
    asm("cvt.rn.f16x2.f32 %0, %1, %2;" : "=r"(r) : "f"(hi), "f"(lo));
    return r;
}
__device__ __forceinline__ uint32_t smem_u32(const void* p) {
    uint32_t a;
    asm("{ .reg .u64 t; cvta.to.shared.u64 t, %1; cvt.u32.u64 %0, t; }" : "=r"(a) : "l"(p));
    return a;
}
#define CP_ASYNC16(dst, src, sz) \
    asm volatile("cp.async.cg.shared.global [%0], [%1], 16, %2;" \
                 :: "r"(dst), "l"(src), "r"(sz) : "memory")
#define CP_COMMIT() asm volatile("cp.async.commit_group;" ::: "memory")
#define CP_WAIT(n)  asm volatile("cp.async.wait_group %0;" :: "n"(n) : "memory")
#define LDSM_X4(r0, r1, r2, r3, addr) \
    asm volatile("ldmatrix.sync.aligned.m8n8.x4.shared.b16 {%0,%1,%2,%3}, [%4];" \
                 : "=r"(r0), "=r"(r1), "=r"(r2), "=r"(r3) : "r"(addr))
#define LDSM_X4_T(r0, r1, r2, r3, addr) \
    asm volatile("ldmatrix.sync.aligned.m8n8.x4.trans.shared.b16 {%0,%1,%2,%3}, [%4];" \
                 : "=r"(r0), "=r"(r1), "=r"(r2), "=r"(r3) : "r"(addr))
#define MMA_F16(d, a, b0, b1) \
    asm volatile( \
        "mma.sync.aligned.m16n8k16.row.col.f32.f16.f16.f32 " \
        "{%0,%1,%2,%3}, {%4,%5,%6,%7}, {%8,%9}, {%0,%1,%2,%3};" \
        : "+f"((d)[0]), "+f"((d)[1]), "+f"((d)[2]), "+f"((d)[3]) \
        : "r"((a)[0]), "r"((a)[1]), "r"((a)[2]), "r"((a)[3]), "r"(b0), "r"(b1))

// ================= one-time fp32 -> fp16 convert (streaming) =================
__global__ void convert_fp16_kernel(const float4* __restrict__ src, uint2* __restrict__ dst) {
    size_t i = (size_t)blockIdx.x * 256 + threadIdx.x;
    float4 v = __ldcs(src + i);
    __stcs(dst + i, make_uint2(f2h2(v.x, v.y), f2h2(v.z, v.w)));
}

// ================= router (warp-per-token) =================
__global__ void init_kernel() {
    if (threadIdx.x < E_NUM) g_counts[threadIdx.x] = 0;
}

__global__ __launch_bounds__(256)
void router_kernel(const float* __restrict__ x, const float* __restrict__ gw) {
    const int lane = threadIdx.x & 31;
    const int t = blockIdx.x * 8 + (threadIdx.x >> 5);
    const float* xr = x + (size_t)t * D_DIM;

    float acc[E_NUM];
#pragma unroll
    for (int e = 0; e < E_NUM; e++) acc[e] = 0.f;
#pragma unroll
    for (int i = 0; i < D_DIM / 32; i++) {
        int d = i * 32 + lane;
        float xv = xr[d];
        const float* g = gw + d * E_NUM;
#pragma unroll
        for (int e = 0; e < E_NUM; e++) acc[e] = fmaf(xv, g[e], acc[e]);
    }
#pragma unroll
    for (int e = 0; e < E_NUM; e++)
#pragma unroll
        for (int off = 16; off > 0; off >>= 1)
            acc[e] += __shfl_down_sync(0xffffffffu, acc[e], off);

    if (lane == 0) {
        float m = acc[0];
#pragma unroll
        for (int e = 1; e < E_NUM; e++) m = fmaxf(m, acc[e]);
        float p[E_NUM], sum = 0.f;
#pragma unroll
        for (int e = 0; e < E_NUM; e++) { p[e] = expf(acc[e] - m); sum += p[e]; }
        float inv = 1.f / sum;
#pragma unroll
        for (int e = 0; e < E_NUM; e++) { p[e] *= inv; g_probs[t * E_NUM + e] = p[e]; }
        int i0 = 0;
#pragma unroll
        for (int e = 1; e < E_NUM; e++) if (p[e] > p[i0]) i0 = e;
        int i1 = (i0 == 0) ? 1 : 0;
#pragma unroll
        for (int e = 0; e < E_NUM; e++) if (e != i0 && p[e] > p[i1]) i1 = e;
        float wn = p[i0] + p[i1];
        g_topk_idx[t * 2 + 0] = i0;
        g_topk_idx[t * 2 + 1] = i1;
        g_topk_w[t * 2 + 0] = p[i0] / wn;
        g_topk_w[t * 2 + 1] = p[i1] / wn;
        atomicAdd(&g_counts[i0], 1);
        atomicAdd(&g_counts[i1], 1);
    }
}

__global__ void offsets_kernel() {
    if (threadIdx.x == 0) {
        int o = 0, mt = 0;
        g_mtile_prefix[0] = 0;
        for (int e = 0; e < E_NUM; e++) {
            g_offsets[e] = o;
            o += g_counts[e];
            mt += (g_counts[e] + BM - 1) / BM;
            g_mtile_prefix[e + 1] = mt;
            g_cursor[e] = 0;
        }
        g_offsets[E_NUM] = o;
    }
}

__global__ void scatter_pos_kernel() {
    int idx = blockIdx.x * 256 + threadIdx.x;
    if (idx >= NSLOT) return;
    int e = g_topk_idx[idx];
    int pos = g_offsets[e] + atomicAdd(&g_cursor[e], 1);
    g_slot_token[pos] = idx >> 1;
    g_slot_w[pos]     = g_topk_w[idx];
    g_slot_of[idx]    = pos;
}

// SMEM formats: A row r (64B): chunk c at r*64 + 16*(c ^ ((r>>1)&3)).
//               B k-row (128B): chunk c at k*128 + 16*(c ^ (k&7)).

// ================= FFN1: H = silu(X Wg) * (X Wu) =================
__global__ __launch_bounds__(128, 2)
void ffn1_kernel() {
    extern __shared__ __align__(16) uint8_t smem[];
    const uint32_t sbase = smem_u32(smem);   // per stage 16KB: A@0, Bg@8192, Bu@12288

    const int mb = blockIdx.x, nb = blockIdx.y;
    if (mb >= g_mtile_prefix[E_NUM]) return;
    int e = 0;
    while (mb >= g_mtile_prefix[e + 1]) e++;
    const int m0   = g_offsets[e] + (mb - g_mtile_prefix[e]) * BM;
    const int mmax = g_offsets[e + 1];

    const int tid = threadIdx.x, lane = tid & 31, wid = tid >> 5;
    const int wm = wid >> 1, wn = wid & 1;

    const int rbase = tid >> 2, chA = tid & 3;
    const int kbB = tid >> 3, chB = tid & 7;
    const char* aSrc[4];
    uint32_t    aDst[4], aSz[4];
#pragma unroll
    for (int rr = 0; rr < 4; rr++) {
        int row = rbase + 32 * rr;
        int gr  = m0 + row;
        int ok  = gr < mmax;
        int tok = ok ? g_slot_token[gr] : 0;
        aSrc[rr] = (const char*)g_xh + (size_t)tok * D_DIM * 2 + chA * 16;
        aDst[rr] = row * 64 + 16 * (chA ^ ((row >> 1) & 3));
        aSz[rr]  = ok ? 16u : 0u;
    }
    const char* gSrc[2];
    const char* uSrc[2];
    uint32_t    bDst[2];
#pragma unroll
    for (int i = 0; i < 2; i++) {
        int k = kbB + 16 * i;
        size_t off = (((size_t)e * D_DIM + k) * I_DIM + (size_t)nb * BN) * 2 + chB * 16;
        gSrc[i] = (const char*)g_Wgh + off;
        uSrc[i] = (const char*)g_Wuh + off;
        bDst[i] = k * 128 + 16 * (chB ^ (k & 7));
    }

#define FFN1_ISSUE(BUF, KC)                                                     \
    do {                                                                        \
        uint32_t sb = sbase + (BUF) * 16384;                                    \
        _Pragma("unroll")                                                       \
        for (int rr = 0; rr < 4; rr++)                                          \
            CP_ASYNC16(sb + aDst[rr], aSrc[rr] + (size_t)(KC) * 64, aSz[rr]);   \
        _Pragma("unroll")                                                       \
        for (int i = 0; i < 2; i++) {                                           \
            size_t ko = (size_t)(KC) * BK * I_DIM * 2;                          \
            CP_ASYNC16(sb + 8192  + bDst[i], gSrc[i] + ko, 16u);                \
            CP_ASYNC16(sb + 12288 + bDst[i], uSrc[i] + ko, 16u);                \
        }                                                                       \
    } while (0)

    float accg[4][4][4], accu[4][4][4];
#pragma unroll
    for (int i = 0; i < 4; i++)
#pragma unroll
        for (int j = 0; j < 4; j++)
#pragma unroll
            for (int k = 0; k < 4; k++) { accg[i][j][k] = 0.f; accu[i][j][k] = 0.f; }

    const int NC = D_DIM / BK;   // 32
#pragma unroll
    for (int s = 0; s < NSTAGE - 1; s++) { FFN1_ISSUE(s, s); CP_COMMIT(); }

    for (int kc = 0; kc < NC; kc++) {
        CP_WAIT(NSTAGE - 2);
        __syncthreads();
        int nk = kc + NSTAGE - 1;
        if (nk < NC) FFN1_ISSUE(nk & (NSTAGE - 1), nk);
        CP_COMMIT();

        const uint32_t abase = sbase + (kc & (NSTAGE - 1)) * 16384;
#pragma unroll
        for (int ks = 0; ks < 2; ks++) {
            uint32_t a[4][4];
#pragma unroll
            for (int mf = 0; mf < 4; mf++) {
                int r  = wm * 64 + mf * 16 + (lane & 15);
                int lc = ks * 2 + (lane >> 4);
                LDSM_X4(a[mf][0], a[mf][1], a[mf][2], a[mf][3],
                        abase + r * 64 + 16 * (lc ^ ((r >> 1) & 3)));
            }
            uint32_t bg[2][4], bu[2][4];
#pragma unroll
            for (int np = 0; np < 2; np++) {
                int k  = ks * 16 + ((lane >> 3) & 1) * 8 + (lane & 7);
                int nl = wn * 32 + np * 16 + (lane >> 4) * 8;
                uint32_t off = k * 128 + 16 * ((nl >> 3) ^ (k & 7));
                LDSM_X4_T(bg[np][0], bg[np][1], bg[np][2], bg[np][3], abase + 8192 + off);
                LDSM_X4_T(bu[np][0], bu[np][1], bu[np][2], bu[np][3], abase + 12288 + off);
            }
#pragma unroll
            for (int mf = 0; mf < 4; mf++)
#pragma unroll
                for (int nf = 0; nf < 4; nf++) {
                    MMA_F16(accg[mf][nf], a[mf], bg[nf >> 1][(nf & 1) * 2],
                            bg[nf >> 1][(nf & 1) * 2 + 1]);
                    MMA_F16(accu[mf][nf], a[mf], bu[nf >> 1][(nf & 1) * 2],
                            bu[nf >> 1][(nf & 1) * 2 + 1]);
                }
        }
    }

#pragma unroll
    for (int mf = 0; mf < 4; mf++) {
        int r0 = m0 + wm * 64 + mf * 16 + (lane >> 2);
        int r1 = r0 + 8;
#pragma unroll
        for (int nf = 0; nf < 4; nf++) {
            int col = nb * BN + wn * 32 + nf * 8 + (lane & 3) * 2;
            if (r0 < mmax) {
                float g0 = accg[mf][nf][0], g1 = accg[mf][nf][1];
                float h0 = g0 / (1.f + expf(-g0)) * accu[mf][nf][0];
                float h1 = g1 / (1.f + expf(-g1)) * accu[mf][nf][1];
                *(uint32_t*)(g_H + (size_t)r0 * I_DIM + col) = f2h2(h0, h1);
            }
            if (r1 < mmax) {
                float g2 = accg[mf][nf][2], g3 = accg[mf][nf][3];
                float h2 = g2 / (1.f + expf(-g2)) * accu[mf][nf][2];
                float h3 = g3 / (1.f + expf(-g3)) * accu[mf][nf][3];
                *(uint32_t*)(g_H + (size_t)r1 * I_DIM + col) = f2h2(h2, h3);
            }
        }
    }
}

// ================= FFN2: Y = (H Wd) * slot_w =================
__global__ __launch_bounds__(128, 3)
void ffn2_kernel() {
    extern __shared__ __align__(16) uint8_t smem[];
    const uint32_t sbase = smem_u32(smem);   // per stage 12KB: A@0, B@8192

    const int mb = blockIdx.x, nb = blockIdx.y;
    if (mb >= g_mtile_prefix[E_NUM]) return;
    int e = 0;
    while (mb >= g_mtile_prefix[e + 1]) e++;
    const int m0   = g_offsets[e] + (mb - g_mtile_prefix[e]) * BM;
    const int mmax = g_offsets[e + 1];

    const int tid = threadIdx.x, lane = tid & 31, wid = tid >> 5;
    const int wm = wid >> 1, wn = wid & 1;

    const int rbase = tid >> 2, chA = tid & 3;
    const int kbB = tid >> 3, chB = tid & 7;
    const char* aSrc[4];
    uint32_t    aDst[4], aSz[4];
#pragma unroll
    for (int rr = 0; rr < 4; rr++) {
        int row = rbase + 32 * rr;
        int gr  = m0 + row;
        int ok  = gr < mmax;
        aSrc[rr] = (const char*)g_H + (size_t)(ok ? gr : 0) * I_DIM * 2 + chA * 16;
        aDst[rr] = row * 64 + 16 * (chA ^ ((row >> 1) & 3));
        aSz[rr]  = ok ? 16u : 0u;
    }
    const char* dSrc[2];
    uint32_t    bDst[2];
#pragma unroll
    for (int i = 0; i < 2; i++) {
        int k = kbB + 16 * i;
        dSrc[i] = (const char*)g_Wdh +
                  (((size_t)e * I_DIM + k) * D_DIM + (size_t)nb * BN) * 2 + chB * 16;
        bDst[i] = k * 128 + 16 * (chB ^ (k & 7));
    }

#define FFN2_ISSUE(BUF, KC)                                                     \
    do {                                                                        \
        uint32_t sb = sbase + (BUF) * 12288;                                    \
        _Pragma("unroll")                                                       \
        for (int rr = 0; rr < 4; rr++)                                          \
            CP_ASYNC16(sb + aDst[rr], aSrc[rr] + (size_t)(KC) * 64, aSz[rr]);   \
        _Pragma("unroll")                                                       \
        for (int i = 0; i < 2; i++)                                             \
            CP_ASYNC16(sb + 8192 + bDst[i],                                     \
                       dSrc[i] + (size_t)(KC) * BK * D_DIM * 2, 16u);           \
    } while (0)

    float acc[4][4][4];
#pragma unroll
    for (int i = 0; i < 4; i++)
#pragma unroll
        for (int j = 0; j < 4; j++)
#pragma unroll
            for (int k = 0; k < 4; k++) acc[i][j][k] = 0.f;

    const int NC = I_DIM / BK;   // 88
#pragma unroll
    for (int s = 0; s < NSTAGE - 1; s++) { FFN2_ISSUE(s, s); CP_COMMIT(); }

    for (int kc = 0; kc < NC; kc++) {
        CP_WAIT(NSTAGE - 2);
        __syncthreads();
        int nk = kc + NSTAGE - 1;
        if (nk < NC) FFN2_ISSUE(nk & (NSTAGE - 1), nk);
        CP_COMMIT();

        const uint32_t abase = sbase + (kc & (NSTAGE - 1)) * 12288;
#pragma unroll
        for (int ks = 0; ks < 2; ks++) {
            uint32_t a[4][4];
#pragma unroll
            for (int mf = 0; mf < 4; mf++) {
                int r  = wm * 64 + mf * 16 + (lane & 15);
                int lc = ks * 2 + (lane >> 4);
                LDSM_X4(a[mf][0], a[mf][1], a[mf][2], a[mf][3],
                        abase + r * 64 + 16 * (lc ^ ((r >> 1) & 3)));
            }
            uint32_t b[2][4];
#pragma unroll
            for (int np = 0; np < 2; np++) {
                int k  = ks * 16 + ((lane >> 3) & 1) * 8 + (lane & 7);
                int nl = wn * 32 + np * 16 + (lane >> 4) * 8;
                LDSM_X4_T(b[np][0], b[np][1], b[np][2], b[np][3],
                          abase + 8192 + k * 128 + 16 * ((nl >> 3) ^ (k & 7)));
            }
#pragma unroll
            for (int mf = 0; mf < 4; mf++)
#pragma unroll
                for (int nf = 0; nf < 4; nf++)
                    MMA_F16(acc[mf][nf], a[mf], b[nf >> 1][(nf & 1) * 2],
                            b[nf >> 1][(nf & 1) * 2 + 1]);
        }
    }

#pragma unroll
    for (int mf = 0; mf < 4; mf++) {
        int r0 = m0 + wm * 64 + mf * 16 + (lane >> 2);
        int r1 = r0 + 8;
        float w0 = (r0 < mmax) ? g_slot_w[r0] : 0.f;
        float w1 = (r1 < mmax) ? g_slot_w[r1] : 0.f;
#pragma unroll
        for (int nf = 0; nf < 4; nf++) {
            int col = nb * BN + wn * 32 + nf * 8 + (lane & 3) * 2;
            if (r0 < mmax)
                *(float2*)(g_Y + (size_t)r0 * D_DIM + col) =
                    make_float2(acc[mf][nf][0] * w0, acc[mf][nf][1] * w0);
            if (r1 < mmax)
                *(float2*)(g_Y + (size_t)r1 * D_DIM + col) =
                    make_float2(acc[mf][nf][2] * w1, acc[mf][nf][3] * w1);
        }
    }
}

// ================= combine + aux =================
__global__ void combine_kernel(float* __restrict__ out) {
    int t = blockIdx.x;
    int s0 = g_slot_of[t * 2 + 0];
    int s1 = g_slot_of[t * 2 + 1];
    const float4* y0 = (const float4*)(g_Y + (size_t)s0 * D_DIM);
    const float4* y1 = (const float4*)(g_Y + (size_t)s1 * D_DIM);
    float4 a = y0[threadIdx.x], b = y1[threadIdx.x];
    ((float4*)(out + (size_t)t * D_DIM))[threadIdx.x] =
        make_float4(a.x + b.x, a.y + b.y, a.z + b.z, a.w + b.w);
}

__global__ void aux_kernel(float* __restrict__ out, int out_size) {
    __shared__ float red[256];
    __shared__ float esum[E_NUM];
    float part[E_NUM];
#pragma unroll
    for (int e = 0; e < E_NUM; e++) part[e] = 0.f;
    for (int t = threadIdx.x; t < T_TOK; t += 256)
#pragma unroll
        for (int e = 0; e < E_NUM; e++) part[e] += g_probs[t * E_NUM + e];
    for (int e = 0; e < E_NUM; e++) {
        red[threadIdx.x] = part[e];
        __syncthreads();
        for (int off = 128; off > 0; off >>= 1) {
            if (threadIdx.x < off) red[threadIdx.x] += red[threadIdx.x + off];
            __syncthreads();
        }
        if (threadIdx.x == 0) esum[e] = red[0];
        __syncthreads();
    }
    if (threadIdx.x == 0) {
        float aux = 0.f;
        for (int e = 0; e < E_NUM; e++)
            aux += ((float)g_counts[e] / (float)T_TOK) * (esum[e] / (float)T_TOK);
        aux *= 0.01f * (float)E_NUM;
        if (out_size > T_TOK * D_DIM) out[(size_t)T_TOK * D_DIM] = aux;
    }
}

// ================= launch =================
extern "C" void kernel_launch(void* const* d_in, const int* in_sizes, int n_in,
                              void* d_out, int out_size) {
    const float* x      = (const float*)d_in[0];
    const float* gate_w = (const float*)d_in[1];
    const float* Wg     = (const float*)d_in[2];
    const float* Wu     = (const float*)d_in[3];
    const float* Wd     = (const float*)d_in[4];
    float* out = (float*)d_out;

    uint16_t* dxh;  cudaGetSymbolAddress((void**)&dxh,  g_xh);
    uint16_t* dWg;  cudaGetSymbolAddress((void**)&dWg,  g_Wgh);
    uint16_t* dWu;  cudaGetSymbolAddress((void**)&dWu,  g_Wuh);
    uint16_t* dWd;  cudaGetSymbolAddress((void**)&dWd,  g_Wdh);

    cudaFuncSetAttribute(ffn1_kernel, cudaFuncAttributeMaxDynamicSharedMemorySize,
                         NSTAGE * 16384);
    cudaFuncSetAttribute(ffn2_kernel, cudaFuncAttributeMaxDynamicSharedMemorySize,
                         NSTAGE * 12288);

    const int WQ = E_NUM * D_DIM * I_DIM / 4 / 256;   // 45056 blocks
    convert_fp16_kernel<<<T_TOK * D_DIM / 4 / 256, 256>>>((const float4*)x, (uint2*)dxh);
    convert_fp16_kernel<<<WQ, 256>>>((const float4*)Wg, (uint2*)dWg);
    convert_fp16_kernel<<<WQ, 256>>>((const float4*)Wu, (uint2*)dWu);
    convert_fp16_kernel<<<WQ, 256>>>((const float4*)Wd, (uint2*)dWd);

    init_kernel<<<1, 32>>>();
    router_kernel<<<T_TOK / 8, 256>>>(x, gate_w);
    offsets_kernel<<<1, 32>>>();
    scatter_pos_kernel<<<(NSLOT + 255) / 256, 256>>>();

    dim3 g1(MAX_MT, I_DIM / BN);   // 144 x 44
    ffn1_kernel<<<g1, 128, NSTAGE * 16384>>>();
    dim3 g2(MAX_MT, D_DIM / BN);   // 144 x 16
    ffn2_kernel<<<g2, 128, NSTAGE * 12288>>>();

    combine_kernel<<<T_TOK, 256>>>(out);
    aux_kernel<<<1, 256>>>(out, out_size);
}

// round 10
// speedup vs baseline: 2.2194x; 1.0427x over previous
#include <cuda_runtime.h>
#include <cuda_fp16.h>
#include <math.h>
#include <stdint.h>

#define T_TOK 8192
#define D_DIM 1024
#define I_DIM 2816
#define E_NUM 16
#define NSLOT (T_TOK * 2)
#define BM 128
#define BN 64
#define BK 32
#define NSTAGE 4
#define MAX_MT (NSLOT / BM + E_NUM)   // 144

#define WQ4  ((size_t)E_NUM * D_DIM * I_DIM / 4)   // float4 count per weight tensor
#define ZQ4  ((size_t)T_TOK * D_DIM / 4)           // float4 count of output
#define WBLK ((int)(WQ4 / 256))                    // 45056 blocks per weight convert

// ================= static device scratch =================
__device__ float    g_probs[T_TOK * E_NUM];
__device__ int      g_topk_idx[NSLOT];
__device__ float    g_topk_w[NSLOT];
__device__ int      g_counts[E_NUM];
__device__ int      g_offsets[E_NUM + 1];
__device__ int      g_cursor[E_NUM];
__device__ int      g_mtile_prefix[E_NUM + 1];
__device__ int      g_slot_token[NSLOT];
__device__ float    g_slot_w[NSLOT];

__device__ uint16_t g_xh [(size_t)T_TOK * D_DIM];
__device__ uint16_t g_Wgh[(size_t)E_NUM * D_DIM * I_DIM];
__device__ uint16_t g_Wuh[(size_t)E_NUM * D_DIM * I_DIM];
__device__ uint16_t g_Wdh[(size_t)E_NUM * I_DIM * D_DIM];
__device__ uint16_t g_H  [(size_t)NSLOT * I_DIM];

// ================= helpers =================
__device__ __forceinline__ uint32_t f2h2(float lo, float hi) {
    uint32_t r;
    asm("cvt.rn.f16x2.f32 %0, %1, %2;" : "=r"(r) : "f"(hi), "f"(lo));
    return r;
}
__device__ __forceinline__ uint32_t smem_u32(const void* p) {
    uint32_t a;
    asm("{ .reg .u64 t; cvta.to.shared.u64 t, %1; cvt.u32.u64 %0, t; }" : "=r"(a) : "l"(p));
    return a;
}
__device__ __forceinline__ void red_add(float* p, float v) {
    asm volatile("red.global.add.f32 [%0], %1;" :: "l"(p), "f"(v) : "memory");
}
#define CP_ASYNC16(dst, src, sz) \
    asm volatile("cp.async.cg.shared.global [%0], [%1], 16, %2;" \
                 :: "r"(dst), "l"(src), "r"(sz) : "memory")
#define CP_COMMIT() asm volatile("cp.async.commit_group;" ::: "memory")
#define CP_WAIT(n)  asm volatile("cp.async.wait_group %0;" :: "n"(n) : "memory")
#define LDSM_X4(r0, r1, r2, r3, addr) \
    asm volatile("ldmatrix.sync.aligned.m8n8.x4.shared.b16 {%0,%1,%2,%3}, [%4];" \
                 : "=r"(r0), "=r"(r1), "=r"(r2), "=r"(r3) : "r"(addr))
#define LDSM_X4_T(r0, r1, r2, r3, addr) \
    asm volatile("ldmatrix.sync.aligned.m8n8.x4.trans.shared.b16 {%0,%1,%2,%3}, [%4];" \
                 : "=r"(r0), "=r"(r1), "=r"(r2), "=r"(r3) : "r"(addr))
#define MMA_F16(d, a, b0, b1) \
    asm volatile( \
        "mma.sync.aligned.m16n8k16.row.col.f32.f16.f16.f32 " \
        "{%0,%1,%2,%3}, {%4,%5,%6,%7}, {%8,%9}, {%0,%1,%2,%3};" \
        : "+f"((d)[0]), "+f"((d)[1]), "+f"((d)[2]), "+f"((d)[3]) \
        : "r"((a)[0]), "r"((a)[1]), "r"((a)[2]), "r"((a)[3]), "r"(b0), "r"(b1))

// ================= init =================
__global__ void init_kernel() {
    if (threadIdx.x < E_NUM) g_counts[threadIdx.x] = 0;
}

// ================= prep: router (+x->fp16) fused with Wg/Wu converts =================
__global__ __launch_bounds__(256)
void prep_kernel(const float* __restrict__ x, const float* __restrict__ gw,
                 const float4* __restrict__ Wg, const float4* __restrict__ Wu) {
    const int b = blockIdx.x;
    if (b >= 1024) {
        // weight converts
        size_t i = (size_t)(b - 1024) * 256 + threadIdx.x;
        if (i < WQ4) {
            float4 v = __ldcs(Wg + i);
            __stcs((uint2*)g_Wgh + i, make_uint2(f2h2(v.x, v.y), f2h2(v.z, v.w)));
        } else {
            i -= WQ4;
            float4 v = __ldcs(Wu + i);
            __stcs((uint2*)g_Wuh + i, make_uint2(f2h2(v.x, v.y), f2h2(v.z, v.w)));
        }
        return;
    }
    // router: warp per token; also emits fp16 copy of the token row
    const int lane = threadIdx.x & 31;
    const int t = b * 8 + (threadIdx.x >> 5);
    const float* xr = x + (size_t)t * D_DIM;

    // fp16 copy of x row
    const float2* xr2 = (const float2*)xr;
    uint32_t* xhr = (uint32_t*)(g_xh + (size_t)t * D_DIM);
#pragma unroll
    for (int i = 0; i < D_DIM / 64; i++) {
        float2 v = xr2[i * 32 + lane];
        xhr[i * 32 + lane] = f2h2(v.x, v.y);
    }

    float acc[E_NUM];
#pragma unroll
    for (int e = 0; e < E_NUM; e++) acc[e] = 0.f;
#pragma unroll
    for (int i = 0; i < D_DIM / 32; i++) {
        int d = i * 32 + lane;
        float xv = xr[d];
        const float* g = gw + d * E_NUM;
#pragma unroll
        for (int e = 0; e < E_NUM; e++) acc[e] = fmaf(xv, g[e], acc[e]);
    }
#pragma unroll
    for (int e = 0; e < E_NUM; e++)
#pragma unroll
        for (int off = 16; off > 0; off >>= 1)
            acc[e] += __shfl_down_sync(0xffffffffu, acc[e], off);

    if (lane == 0) {
        float m = acc[0];
#pragma unroll
        for (int e = 1; e < E_NUM; e++) m = fmaxf(m, acc[e]);
        float p[E_NUM], sum = 0.f;
#pragma unroll
        for (int e = 0; e < E_NUM; e++) { p[e] = expf(acc[e] - m); sum += p[e]; }
        float inv = 1.f / sum;
#pragma unroll
        for (int e = 0; e < E_NUM; e++) { p[e] *= inv; g_probs[t * E_NUM + e] = p[e]; }
        int i0 = 0;
#pragma unroll
        for (int e = 1; e < E_NUM; e++) if (p[e] > p[i0]) i0 = e;
        int i1 = (i0 == 0) ? 1 : 0;
#pragma unroll
        for (int e = 0; e < E_NUM; e++) if (e != i0 && p[e] > p[i1]) i1 = e;
        float wn = p[i0] + p[i1];
        g_topk_idx[t * 2 + 0] = i0;
        g_topk_idx[t * 2 + 1] = i1;
        g_topk_w[t * 2 + 0] = p[i0] / wn;
        g_topk_w[t * 2 + 1] = p[i1] / wn;
        atomicAdd(&g_counts[i0], 1);
        atomicAdd(&g_counts[i1], 1);
    }
}

__global__ void offsets_kernel() {
    if (threadIdx.x == 0) {
        int o = 0, mt = 0;
        g_mtile_prefix[0] = 0;
        for (int e = 0; e < E_NUM; e++) {
            g_offsets[e] = o;
            o += g_counts[e];
            mt += (g_counts[e] + BM - 1) / BM;
            g_mtile_prefix[e + 1] = mt;
            g_cursor[e] = 0;
        }
        g_offsets[E_NUM] = o;
    }
}

__global__ void scatter_pos_kernel() {
    int idx = blockIdx.x * 256 + threadIdx.x;
    if (idx >= NSLOT) return;
    int e = g_topk_idx[idx];
    int pos = g_offsets[e] + atomicAdd(&g_cursor[e], 1);
    g_slot_token[pos] = idx >> 1;
    g_slot_w[pos]     = g_topk_w[idx];
}

// ================= Wd convert + output zero (side stream, hidden under FFN1) ====
__global__ void wdzero_kernel(const float4* __restrict__ Wd, float4* __restrict__ out4) {
    size_t i = (size_t)blockIdx.x * 256 + threadIdx.x;
    if (i < WQ4) {
        float4 v = __ldcs(Wd + i);
        __stcs((uint2*)g_Wdh + i, make_uint2(f2h2(v.x, v.y), f2h2(v.z, v.w)));
    } else {
        size_t j = i - WQ4;
        if (j < ZQ4) out4[j] = make_float4(0.f, 0.f, 0.f, 0.f);
    }
}

// SMEM formats: A row r (64B): chunk c at r*64 + 16*(c ^ ((r>>1)&3)).
//               B k-row (128B): chunk c at k*128 + 16*(c ^ (k&7)).

// ================= FFN1: H = silu(X Wg) * (X Wu) =================
__global__ __launch_bounds__(128, 2)
void ffn1_kernel() {
    extern __shared__ __align__(16) uint8_t smem[];
    const uint32_t sbase = smem_u32(smem);   // per stage 16KB: A@0, Bg@8192, Bu@12288

    const int mb = blockIdx.x, nb = blockIdx.y;
    if (mb >= g_mtile_prefix[E_NUM]) return;
    int e = 0;
    while (mb >= g_mtile_prefix[e + 1]) e++;
    const int m0   = g_offsets[e] + (mb - g_mtile_prefix[e]) * BM;
    const int mmax = g_offsets[e + 1];

    const int tid = threadIdx.x, lane = tid & 31, wid = tid >> 5;
    const int wm = wid >> 1, wn = wid & 1;

    const int rbase = tid >> 2, chA = tid & 3;
    const int kbB = tid >> 3, chB = tid & 7;
    const char* aSrc[4];
    uint32_t    aDst[4], aSz[4];
#pragma unroll
    for (int rr = 0; rr < 4; rr++) {
        int row = rbase + 32 * rr;
        int gr  = m0 + row;
        int ok  = gr < mmax;
        int tok = ok ? g_slot_token[gr] : 0;
        aSrc[rr] = (const char*)g_xh + (size_t)tok * D_DIM * 2 + chA * 16;
        aDst[rr] = row * 64 + 16 * (chA ^ ((row >> 1) & 3));
        aSz[rr]  = ok ? 16u : 0u;
    }
    const char* gSrc[2];
    const char* uSrc[2];
    uint32_t    bDst[2];
#pragma unroll
    for (int i = 0; i < 2; i++) {
        int k = kbB + 16 * i;
        size_t off = (((size_t)e * D_DIM + k) * I_DIM + (size_t)nb * BN) * 2 + chB * 16;
        gSrc[i] = (const char*)g_Wgh + off;
        uSrc[i] = (const char*)g_Wuh + off;
        bDst[i] = k * 128 + 16 * (chB ^ (k & 7));
    }

#define FFN1_ISSUE(BUF, KC)                                                     \
    do {                                                                        \
        uint32_t sb = sbase + (BUF) * 16384;                                    \
        _Pragma("unroll")                                                       \
        for (int rr = 0; rr < 4; rr++)                                          \
            CP_ASYNC16(sb + aDst[rr], aSrc[rr] + (size_t)(KC) * 64, aSz[rr]);   \
        _Pragma("unroll")                                                       \
        for (int i = 0; i < 2; i++) {                                           \
            size_t ko = (size_t)(KC) * BK * I_DIM * 2;                          \
            CP_ASYNC16(sb + 8192  + bDst[i], gSrc[i] + ko, 16u);                \
            CP_ASYNC16(sb + 12288 + bDst[i], uSrc[i] + ko, 16u);                \
        }                                                                       \
    } while (0)

    float accg[4][4][4], accu[4][4][4];
#pragma unroll
    for (int i = 0; i < 4; i++)
#pragma unroll
        for (int j = 0; j < 4; j++)
#pragma unroll
            for (int k = 0; k < 4; k++) { accg[i][j][k] = 0.f; accu[i][j][k] = 0.f; }

    const int NC = D_DIM / BK;   // 32
#pragma unroll
    for (int s = 0; s < NSTAGE - 1; s++) { FFN1_ISSUE(s, s); CP_COMMIT(); }

    for (int kc = 0; kc < NC; kc++) {
        CP_WAIT(NSTAGE - 2);
        __syncthreads();
        int nk = kc + NSTAGE - 1;
        if (nk < NC) FFN1_ISSUE(nk & (NSTAGE - 1), nk);
        CP_COMMIT();

        const uint32_t abase = sbase + (kc & (NSTAGE - 1)) * 16384;
#pragma unroll
        for (int ks = 0; ks < 2; ks++) {
            uint32_t a[4][4];
#pragma unroll
            for (int mf = 0; mf < 4; mf++) {
                int r  = wm * 64 + mf * 16 + (lane & 15);
                int lc = ks * 2 + (lane >> 4);
                LDSM_X4(a[mf][0], a[mf][1], a[mf][2], a[mf][3],
                        abase + r * 64 + 16 * (lc ^ ((r >> 1) & 3)));
            }
            uint32_t bg[2][4], bu[2][4];
#pragma unroll
            for (int np = 0; np < 2; np++) {
                int k  = ks * 16 + ((lane >> 3) & 1) * 8 + (lane & 7);
                int nl = wn * 32 + np * 16 + (lane >> 4) * 8;
                uint32_t off = k * 128 + 16 * ((nl >> 3) ^ (k & 7));
                LDSM_X4_T(bg[np][0], bg[np][1], bg[np][2], bg[np][3], abase + 8192 + off);
                LDSM_X4_T(bu[np][0], bu[np][1], bu[np][2], bu[np][3], abase + 12288 + off);
            }
#pragma unroll
            for (int mf = 0; mf < 4; mf++)
#pragma unroll
                for (int nf = 0; nf < 4; nf++) {
                    MMA_F16(accg[mf][nf], a[mf], bg[nf >> 1][(nf & 1) * 2],
                            bg[nf >> 1][(nf & 1) * 2 + 1]);
                    MMA_F16(accu[mf][nf], a[mf], bu[nf >> 1][(nf & 1) * 2],
                            bu[nf >> 1][(nf & 1) * 2 + 1]);
                }
        }
    }

#pragma unroll
    for (int mf = 0; mf < 4; mf++) {
        int r0 = m0 + wm * 64 + mf * 16 + (lane >> 2);
        int r1 = r0 + 8;
#pragma unroll
        for (int nf = 0; nf < 4; nf++) {
            int col = nb * BN + wn * 32 + nf * 8 + (lane & 3) * 2;
            if (r0 < mmax) {
                float g0 = accg[mf][nf][0], g1 = accg[mf][nf][1];
                float h0 = g0 / (1.f + expf(-g0)) * accu[mf][nf][0];
                float h1 = g1 / (1.f + expf(-g1)) * accu[mf][nf][1];
                *(uint32_t*)(g_H + (size_t)r0 * I_DIM + col) = f2h2(h0, h1);
            }
            if (r1 < mmax) {
                float g2 = accg[mf][nf][2], g3 = accg[mf][nf][3];
                float h2 = g2 / (1.f + expf(-g2)) * accu[mf][nf][2];
                float h3 = g3 / (1.f + expf(-g3)) * accu[mf][nf][3];
                *(uint32_t*)(g_H + (size_t)r1 * I_DIM + col) = f2h2(h2, h3);
            }
        }
    }
}

// ================= FFN2: out += (H Wd) * slot_w  (direct red) =================
__global__ __launch_bounds__(128, 3)
void ffn2_kernel(float* __restrict__ out) {
    extern __shared__ __align__(16) uint8_t smem[];
    const uint32_t sbase = smem_u32(smem);   // per stage 12KB: A@0, B@8192

    const int mb = blockIdx.x, nb = blockIdx.y;
    if (mb >= g_mtile_prefix[E_NUM]) return;
    int e = 0;
    while (mb >= g_mtile_prefix[e + 1]) e++;
    const int m0   = g_offsets[e] + (mb - g_mtile_prefix[e]) * BM;
    const int mmax = g_offsets[e + 1];

    const int tid = threadIdx.x, lane = tid & 31, wid = tid >> 5;
    const int wm = wid >> 1, wn = wid & 1;

    const int rbase = tid >> 2, chA = tid & 3;
    const int kbB = tid >> 3, chB = tid & 7;
    const char* aSrc[4];
    uint32_t    aDst[4], aSz[4];
#pragma unroll
    for (int rr = 0; rr < 4; rr++) {
        int row = rbase + 32 * rr;
        int gr  = m0 + row;
        int ok  = gr < mmax;
        aSrc[rr] = (const char*)g_H + (size_t)(ok ? gr : 0) * I_DIM * 2 + chA * 16;
        aDst[rr] = row * 64 + 16 * (chA ^ ((row >> 1) & 3));
        aSz[rr]  = ok ? 16u : 0u;
    }
    const char* dSrc[2];
    uint32_t    bDst[2];
#pragma unroll
    for (int i = 0; i < 2; i++) {
        int k = kbB + 16 * i;
        dSrc[i] = (const char*)g_Wdh +
                  (((size_t)e * I_DIM + k) * D_DIM + (size_t)nb * BN) * 2 + chB * 16;
        bDst[i] = k * 128 + 16 * (chB ^ (k & 7));
    }

#define FFN2_ISSUE(BUF, KC)                                                     \
    do {                                                                        \
        uint32_t sb = sbase + (BUF) * 12288;                                    \
        _Pragma("unroll")                                                       \
        for (int rr = 0; rr < 4; rr++)                                          \
            CP_ASYNC16(sb + aDst[rr], aSrc[rr] + (size_t)(KC) * 64, aSz[rr]);   \
        _Pragma("unroll")                                                       \
        for (int i = 0; i < 2; i++)                                             \
            CP_ASYNC16(sb + 8192 + bDst[i],                                     \
                       dSrc[i] + (size_t)(KC) * BK * D_DIM * 2, 16u);           \
    } while (0)

    float acc[4][4][4];
#pragma unroll
    for (int i = 0; i < 4; i++)
#pragma unroll
        for (int j = 0; j < 4; j++)
#pragma unroll
            for (int k = 0; k < 4; k++) acc[i][j][k] = 0.f;

    const int NC = I_DIM / BK;   // 88
#pragma unroll
    for (int s = 0; s < NSTAGE - 1; s++) { FFN2_ISSUE(s, s); CP_COMMIT(); }

    for (int kc = 0; kc < NC; kc++) {
        CP_WAIT(NSTAGE - 2);
        __syncthreads();
        int nk = kc + NSTAGE - 1;
        if (nk < NC) FFN2_ISSUE(nk & (NSTAGE - 1), nk);
        CP_COMMIT();

        const uint32_t abase = sbase + (kc & (NSTAGE - 1)) * 12288;
#pragma unroll
        for (int ks = 0; ks < 2; ks++) {
            uint32_t a[4][4];
#pragma unroll
            for (int mf = 0; mf < 4; mf++) {
                int r  = wm * 64 + mf * 16 + (lane & 15);
                int lc = ks * 2 + (lane >> 4);
                LDSM_X4(a[mf][0], a[mf][1], a[mf][2], a[mf][3],
                        abase + r * 64 + 16 * (lc ^ ((r >> 1) & 3)));
            }
            uint32_t b[2][4];
#pragma unroll
            for (int np = 0; np < 2; np++) {
                int k  = ks * 16 + ((lane >> 3) & 1) * 8 + (lane & 7);
                int nl = wn * 32 + np * 16 + (lane >> 4) * 8;
                LDSM_X4_T(b[np][0], b[np][1], b[np][2], b[np][3],
                          abase + 8192 + k * 128 + 16 * ((nl >> 3) ^ (k & 7)));
            }
#pragma unroll
            for (int mf = 0; mf < 4; mf++)
#pragma unroll
                for (int nf = 0; nf < 4; nf++)
                    MMA_F16(acc[mf][nf], a[mf], b[nf >> 1][(nf & 1) * 2],
                            b[nf >> 1][(nf & 1) * 2 + 1]);
        }
    }

#pragma unroll
    for (int mf = 0; mf < 4; mf++) {
        int r0 = m0 + wm * 64 + mf * 16 + (lane >> 2);
        int r1 = r0 + 8;
        bool ok0 = r0 < mmax, ok1 = r1 < mmax;
        float w0 = ok0 ? g_slot_w[r0] : 0.f;
        float w1 = ok1 ? g_slot_w[r1] : 0.f;
        int tok0 = ok0 ? g_slot_token[r0] : 0;
        int tok1 = ok1 ? g_slot_token[r1] : 0;
#pragma unroll
        for (int nf = 0; nf < 4; nf++) {
            int col = nb * BN + wn * 32 + nf * 8 + (lane & 3) * 2;
            if (ok0) {
                float* p = out + (size_t)tok0 * D_DIM + col;
                red_add(p,     acc[mf][nf][0] * w0);
                red_add(p + 1, acc[mf][nf][1] * w0);
            }
            if (ok1) {
                float* p = out + (size_t)tok1 * D_DIM + col;
                red_add(p,     acc[mf][nf][2] * w1);
                red_add(p + 1, acc[mf][nf][3] * w1);
            }
        }
    }
}

// ================= aux =================
__global__ void aux_kernel(float* __restrict__ out, int out_size) {
    __shared__ float red[256];
    __shared__ float esum[E_NUM];
    float part[E_NUM];
#pragma unroll
    for (int e = 0; e < E_NUM; e++) part[e] = 0.f;
    for (int t = threadIdx.x; t < T_TOK; t += 256)
#pragma unroll
        for (int e = 0; e < E_NUM; e++) part[e] += g_probs[t * E_NUM + e];
    for (int e = 0; e < E_NUM; e++) {
        red[threadIdx.x] = part[e];
        __syncthreads();
        for (int off = 128; off > 0; off >>= 1) {
            if (threadIdx.x < off) red[threadIdx.x] += red[threadIdx.x + off];
            __syncthreads();
        }
        if (threadIdx.x == 0) esum[e] = red[0];
        __syncthreads();
    }
    if (threadIdx.x == 0) {
        float aux = 0.f;
        for (int e = 0; e < E_NUM; e++)
            aux += ((float)g_counts[e] / (float)T_TOK) * (esum[e] / (float)T_TOK);
        aux *= 0.01f * (float)E_NUM;
        if (out_size > T_TOK * D_DIM) out[(size_t)T_TOK * D_DIM] = aux;
    }
}

// ================= launch =================
extern "C" void kernel_launch(void* const* d_in, const int* in_sizes, int n_in,
                              void* d_out, int out_size) {
    const float* x      = (const float*)d_in[0];
    const float* gate_w = (const float*)d_in[1];
    const float* Wg     = (const float*)d_in[2];
    const float* Wu     = (const float*)d_in[3];
    const float* Wd     = (const float*)d_in[4];
    float* out = (float*)d_out;

    cudaFuncSetAttribute(ffn1_kernel, cudaFuncAttributeMaxDynamicSharedMemorySize,
                         NSTAGE * 16384);
    cudaFuncSetAttribute(ffn2_kernel, cudaFuncAttributeMaxDynamicSharedMemorySize,
                         NSTAGE * 12288);

    cudaStream_t sA;
    cudaStreamCreateWithFlags(&sA, cudaStreamNonBlocking);
    cudaEvent_t evPre, evA;
    cudaEventCreateWithFlags(&evPre, cudaEventDisableTiming);
    cudaEventCreateWithFlags(&evA,  cudaEventDisableTiming);

    init_kernel<<<1, 32>>>();
    prep_kernel<<<1024 + 2 * WBLK, 256>>>(x, gate_w, (const float4*)Wg, (const float4*)Wu);
    offsets_kernel<<<1, 32>>>();
    scatter_pos_kernel<<<(NSLOT + 255) / 256, 256>>>();

    cudaEventRecord(evPre, 0);

    dim3 g1(MAX_MT, I_DIM / BN);   // 144 x 44
    ffn1_kernel<<<g1, 128, NSTAGE * 16384>>>();

    // hide Wd convert + out zeroing under FFN1 on a side stream
    cudaStreamWaitEvent(sA, evPre, 0);
    int wz_blocks = (int)((WQ4 + ZQ4 + 255) / 256);
    wdzero_kernel<<<wz_blocks, 256, 0, sA>>>((const float4*)Wd, (float4*)out);
    cudaEventRecord(evA, sA);
    cudaStreamWaitEvent(0, evA, 0);

    dim3 g2(MAX_MT, D_DIM / BN);   // 144 x 16
    ffn2_kernel<<<g2, 128, NSTAGE * 12288>>>(out);

    aux_kernel<<<1, 256>>>(out, out_size);
}